// round 15
// baseline (speedup 1.0000x reference)
#include <cuda_runtime.h>
#include <cuda_bf16.h>
#include <math.h>
#include <stdint.h>

// ---------------------------------------------------------------------------
// DistMultDecoder: out[e] = sigmoid( z[src_e] . (W + W^T) . z[dst_e] )
//   Wsym = W + W^T ; Y = Z @ Wsym ; out[e] = sigmoid(dot(Y[src], Z[dst]))
// GEMM: mma.sync bf16 2-term Dekker split  Y = Zh*Wh + Zh*Wl + Zl*Wh
//   (R7 version: direct-A from global, 64 accums, NO min-blocks clamp).
// Edge: flat, 8 lanes/edge, 8 edges/warp, 16 LDG.128 in flight (R8 version).
// ---------------------------------------------------------------------------

#define HID 128
#define MAX_NODES 100000
#define PAD_W 68   // words/row: frag LDS bank = (4g+t) mod 32, conflict-free

__device__ float g_Y[(size_t)MAX_NODES * HID];
__device__ int   g_is64;
__device__ __nv_bfloat16 g_Wh[HID * HID];   // Wsym hi, row-major [n][k]
__device__ __nv_bfloat16 g_Wl[HID * HID];   // Wsym lo

// ------- kernel 1: Wsym = W + W^T -> bf16 hi/lo ; + index-dtype detect ------
__global__ void symm_kernel(const float* __restrict__ W, const int* __restrict__ ei32) {
    if (blockIdx.x == 0 && threadIdx.x == 0) {
        int s = 0;
        #pragma unroll
        for (int i = 1; i < 64; i += 2) s |= ei32[i];
        g_is64 = (s == 0) ? 1 : 0;          // int64 LE small values: odd words all 0
    }
    int i = blockIdx.x * blockDim.x + threadIdx.x;   // 0..16383
    int n = i >> 7, k = i & 127;
    float v = W[n * HID + k] + W[k * HID + n];       // Wsym[n][k]
    __nv_bfloat16 hi = __float2bfloat16(v);
    __nv_bfloat16 lo = __float2bfloat16(v - __bfloat162float(hi));
    g_Wh[i] = hi;
    g_Wl[i] = lo;
}

// ---------------- kernel 2: Y = Z @ Wsym via mma.sync bf16 ------------------
#define MMA16816(D, A0, A1, A2, A3, B0, B1)                                   \
    asm volatile("mma.sync.aligned.m16n8k16.row.col.f32.bf16.bf16.f32 "       \
                 "{%0,%1,%2,%3}, {%4,%5,%6,%7}, {%8,%9}, {%0,%1,%2,%3};"      \
                 : "+f"(D[0]), "+f"(D[1]), "+f"(D[2]), "+f"(D[3])             \
                 : "r"(A0), "r"(A1), "r"(A2), "r"(A3), "r"(B0), "r"(B1))

__device__ __forceinline__ uint32_t bf2_hi(float2 p) {
    __nv_bfloat162 h = __floats2bfloat162_rn(p.x, p.y);
    return *(uint32_t*)&h;
}
__device__ __forceinline__ uint32_t bf2_lo(float2 p, uint32_t hbits) {
    __nv_bfloat162 h = *(__nv_bfloat162*)&hbits;
    __nv_bfloat162 l = __floats2bfloat162_rn(p.x - __bfloat162float(h.x),
                                             p.y - __bfloat162float(h.y));
    return *(uint32_t*)&l;
}

__global__ __launch_bounds__(256) void gemm_mma_kernel(const float* __restrict__ Z, int nrows) {
    extern __shared__ __align__(16) uint32_t sh[];
    uint32_t* WH = sh;                    // 128 x 68 words (bf16x2)
    uint32_t* WL = sh + 128 * PAD_W;

    int tid = threadIdx.x;

    // ---- stage W hi/lo into padded smem (8192 words each, coalesced) ----
    {
        const uint32_t* gwh = (const uint32_t*)g_Wh;
        const uint32_t* gwl = (const uint32_t*)g_Wl;
        #pragma unroll
        for (int i = 0; i < 32; i++) {
            int idx  = tid + 256 * i;        // 0..8191
            int row  = idx >> 6;
            int word = idx & 63;
            WH[row * PAD_W + word] = gwh[idx];
            WL[row * PAD_W + word] = gwl[idx];
        }
    }
    __syncthreads();

    int lane = tid & 31, w = tid >> 5;
    int g = lane >> 2, t = lane & 3;
    int r0 = (w & 3) * 32;        // warp row base within CTA tile
    int n0 = (w >> 2) * 64;       // warp col base

    // Per-thread A rows (clamped for OOB; garbage accumulators never stored)
    int base = blockIdx.x * 128 + r0 + g;
    int rA[4] = { base, base + 8, base + 16, base + 24 };
    const float* zp[4];
    #pragma unroll
    for (int q = 0; q < 4; q++) {
        int r = rA[q] < nrows ? rA[q] : (nrows - 1);
        zp[q] = Z + (size_t)r * HID + 2 * t;
    }

    float d[2][8][4];
    #pragma unroll
    for (int m = 0; m < 2; m++)
        #pragma unroll
        for (int n = 0; n < 8; n++)
            #pragma unroll
            for (int q = 0; q < 4; q++) d[m][n][q] = 0.f;

    #pragma unroll
    for (int ks = 0; ks < 8; ks++) {
        int kb = ks * 16;
        float2 p00 = *(const float2*)(zp[0] + kb);
        float2 p01 = *(const float2*)(zp[0] + kb + 8);
        float2 p10 = *(const float2*)(zp[1] + kb);
        float2 p11 = *(const float2*)(zp[1] + kb + 8);
        float2 q00 = *(const float2*)(zp[2] + kb);
        float2 q01 = *(const float2*)(zp[2] + kb + 8);
        float2 q10 = *(const float2*)(zp[3] + kb);
        float2 q11 = *(const float2*)(zp[3] + kb + 8);

        uint32_t ah[2][4], al[2][4];
        ah[0][0] = bf2_hi(p00);  ah[0][1] = bf2_hi(p10);
        ah[0][2] = bf2_hi(p01);  ah[0][3] = bf2_hi(p11);
        ah[1][0] = bf2_hi(q00);  ah[1][1] = bf2_hi(q10);
        ah[1][2] = bf2_hi(q01);  ah[1][3] = bf2_hi(q11);
        al[0][0] = bf2_lo(p00, ah[0][0]);  al[0][1] = bf2_lo(p10, ah[0][1]);
        al[0][2] = bf2_lo(p01, ah[0][2]);  al[0][3] = bf2_lo(p11, ah[0][3]);
        al[1][0] = bf2_lo(q00, ah[1][0]);  al[1][1] = bf2_lo(q10, ah[1][1]);
        al[1][2] = bf2_lo(q01, ah[1][2]);  al[1][3] = bf2_lo(q11, ah[1][3]);

        int kw = ks * 8 + t;
        #pragma unroll
        for (int n = 0; n < 8; n++) {
            int nb = (n0 + 8 * n + g) * PAD_W + kw;
            uint32_t bh0 = WH[nb], bh1 = WH[nb + 4];
            uint32_t bl0 = WL[nb], bl1 = WL[nb + 4];
            #pragma unroll
            for (int m = 0; m < 2; m++) {
                MMA16816(d[m][n], ah[m][0], ah[m][1], ah[m][2], ah[m][3], bh0, bh1);
                MMA16816(d[m][n], ah[m][0], ah[m][1], ah[m][2], ah[m][3], bl0, bl1);
                MMA16816(d[m][n], al[m][0], al[m][1], al[m][2], al[m][3], bh0, bh1);
            }
        }
    }

    // ---- epilogue: d -> g_Y ----
    #pragma unroll
    for (int m = 0; m < 2; m++) {
        int r = base + 16 * m;
        #pragma unroll
        for (int n = 0; n < 8; n++) {
            int c = n0 + 8 * n + 2 * t;
            if (r < nrows)
                *(float2*)(g_Y + (size_t)r * HID + c) = make_float2(d[m][n][0], d[m][n][1]);
            if (r + 8 < nrows)
                *(float2*)(g_Y + (size_t)(r + 8) * HID + c) = make_float2(d[m][n][2], d[m][n][3]);
        }
    }
}

// ------------------- kernel 3: per-edge gather + dot + sigmoid --------------
// 8 lanes/edge, 8 edges/warp in two 4-edge batches; 16 LDG.128 in flight.
__global__ __launch_bounds__(256) void edge_kernel(const void* __restrict__ ei,
                                                   const float* __restrict__ Z,
                                                   float* __restrict__ out, int E) {
    const unsigned FULL = 0xFFFFFFFFu;
    int gtid  = blockIdx.x * blockDim.x + threadIdx.x;
    int warp  = gtid >> 5;
    int lane  = gtid & 31;
    int grp   = lane >> 3;       // 0..3
    int sub   = lane & 7;        // 0..7

    long long e0 = (long long)warp * 8;
    if (e0 >= E) return;

    long long myidx = 0;
    int is64 = g_is64;
    if (lane < 16) {
        long long e = e0 + (lane & 7);
        if (e >= E) e = 0;
        size_t off = (lane < 8) ? (size_t)e : (size_t)E + (size_t)e;
        if (is64) myidx = ((const long long*)ei)[off];
        else      myidx = ((const int*)ei)[off];
    }
    long long s0 = __shfl_sync(FULL, myidx, grp);
    long long s1 = __shfl_sync(FULL, myidx, 4 + grp);
    long long d0 = __shfl_sync(FULL, myidx, 8 + grp);
    long long d1 = __shfl_sync(FULL, myidx, 12 + grp);

    const float4* Ya0 = (const float4*)(g_Y + (size_t)s0 * HID);
    const float4* Zb0 = (const float4*)(Z   + (size_t)d0 * HID);
    const float4* Ya1 = (const float4*)(g_Y + (size_t)s1 * HID);
    const float4* Zb1 = (const float4*)(Z   + (size_t)d1 * HID);

    float4 a0 = Ya0[sub];       float4 b0 = Zb0[sub];
    float4 a1 = Ya0[sub + 8];   float4 b1 = Zb0[sub + 8];
    float4 a2 = Ya0[sub + 16];  float4 b2 = Zb0[sub + 16];
    float4 a3 = Ya0[sub + 24];  float4 b3 = Zb0[sub + 24];
    float4 c0 = Ya1[sub];       float4 e0v = Zb1[sub];
    float4 c1 = Ya1[sub + 8];   float4 e1v = Zb1[sub + 8];
    float4 c2 = Ya1[sub + 16];  float4 e2v = Zb1[sub + 16];
    float4 c3 = Ya1[sub + 24];  float4 e3v = Zb1[sub + 24];

    float v0 = a0.x * b0.x + a0.y * b0.y + a0.z * b0.z + a0.w * b0.w;
    v0 += a1.x * b1.x + a1.y * b1.y + a1.z * b1.z + a1.w * b1.w;
    v0 += a2.x * b2.x + a2.y * b2.y + a2.z * b2.z + a2.w * b2.w;
    v0 += a3.x * b3.x + a3.y * b3.y + a3.z * b3.z + a3.w * b3.w;

    float v1 = c0.x * e0v.x + c0.y * e0v.y + c0.z * e0v.z + c0.w * e0v.w;
    v1 += c1.x * e1v.x + c1.y * e1v.y + c1.z * e1v.z + c1.w * e1v.w;
    v1 += c2.x * e2v.x + c2.y * e2v.y + c2.z * e2v.z + c2.w * e2v.w;
    v1 += c3.x * e3v.x + c3.y * e3v.y + c3.z * e3v.z + c3.w * e3v.w;

    v0 += __shfl_xor_sync(FULL, v0, 1);
    v1 += __shfl_xor_sync(FULL, v1, 1);
    v0 += __shfl_xor_sync(FULL, v0, 2);
    v1 += __shfl_xor_sync(FULL, v1, 2);
    v0 += __shfl_xor_sync(FULL, v0, 4);
    v1 += __shfl_xor_sync(FULL, v1, 4);

    float vg0 = __shfl_sync(FULL, v0, (lane & 3) << 3);
    float vg1 = __shfl_sync(FULL, v1, (lane & 3) << 3);
    float vg  = (lane < 4) ? vg0 : vg1;

    if (lane < 8) {
        long long e = e0 + lane;
        if (e < E) out[e] = 1.0f / (1.0f + expf(-vg));
    }
}

// ---------------------------------------------------------------------------
extern "C" void kernel_launch(void* const* d_in, const int* in_sizes, int n_in,
                              void* d_out, int out_size) {
    // Map inputs by element count: W = 16384; z = largest; edge_index = the rest.
    int wi = -1;
    for (int i = 0; i < n_in; i++) if (in_sizes[i] == HID * HID) { wi = i; break; }
    int zi = -1;
    for (int i = 0; i < n_in; i++) {
        if (i == wi) continue;
        if (zi < 0 || in_sizes[i] > in_sizes[zi]) zi = i;
    }
    int eii = -1;
    for (int i = 0; i < n_in; i++) if (i != wi && i != zi) { eii = i; break; }

    const float* W  = (const float*)d_in[wi];
    const float* z  = (const float*)d_in[zi];
    const void*  ei = d_in[eii];

    float* out = (float*)d_out;
    int nrows = in_sizes[zi] / HID;
    int E     = in_sizes[eii] / 2;

    symm_kernel<<<64, 256>>>(W, (const int*)ei);

    int smem = 2 * 128 * PAD_W * (int)sizeof(uint32_t);   // 69632 B
    cudaFuncSetAttribute(gemm_mma_kernel, cudaFuncAttributeMaxDynamicSharedMemorySize, smem);
    int gblocks = (nrows + 127) / 128;
    gemm_mma_kernel<<<gblocks, 256, smem>>>(z, nrows);

    int eblocks = (E + 63) / 64;
    edge_kernel<<<eblocks, 256>>>(ei, z, out, E);
}

// round 17
// speedup vs baseline: 1.1754x; 1.1754x over previous
#include <cuda_runtime.h>
#include <cuda_bf16.h>
#include <cuda_fp16.h>
#include <math.h>
#include <stdint.h>

// ---------------------------------------------------------------------------
// DistMultDecoder: out[e] = sigmoid( z[src_e] . (W + W^T) . z[dst_e] )
//   Wsym = W + W^T ; Y = Z @ Wsym ; out[e] = sigmoid(dot(Y[src], Z[dst]))
// GEMM: mma.sync bf16 2-term Dekker split (R8 config, (256,2) clamp).
// Y stored as FP16 (delta_v ~2e-3 << sigma_v=16; rel_err ~2e-4 predicted)
//   -> edge src traffic halved: 1.02 GB -> 0.77 GB at the LTS cap.
// Edge: 8 lanes/edge, 8 edges/warp, 12 LDG.128 in flight per lane.
// ---------------------------------------------------------------------------

#define HID 128
#define MAX_NODES 100000
#define PAD_W 68   // words/row: frag LDS bank = (4g+t) mod 32, conflict-free

__device__ __half g_Yh[(size_t)MAX_NODES * HID];
__device__ int   g_is64;
__device__ __nv_bfloat16 g_Wh[HID * HID];   // Wsym hi, row-major [n][k]
__device__ __nv_bfloat16 g_Wl[HID * HID];   // Wsym lo

// ------- kernel 1: Wsym = W + W^T -> bf16 hi/lo ; + index-dtype detect ------
__global__ void symm_kernel(const float* __restrict__ W, const int* __restrict__ ei32) {
    if (blockIdx.x == 0 && threadIdx.x == 0) {
        int s = 0;
        #pragma unroll
        for (int i = 1; i < 64; i += 2) s |= ei32[i];
        g_is64 = (s == 0) ? 1 : 0;          // int64 LE small values: odd words all 0
    }
    int i = blockIdx.x * blockDim.x + threadIdx.x;   // 0..16383
    int n = i >> 7, k = i & 127;
    float v = W[n * HID + k] + W[k * HID + n];       // Wsym[n][k]
    __nv_bfloat16 hi = __float2bfloat16(v);
    __nv_bfloat16 lo = __float2bfloat16(v - __bfloat162float(hi));
    g_Wh[i] = hi;
    g_Wl[i] = lo;
}

// ---------------- kernel 2: Y = Z @ Wsym via mma.sync bf16 ------------------
#define MMA16816(D, A0, A1, A2, A3, B0, B1)                                   \
    asm volatile("mma.sync.aligned.m16n8k16.row.col.f32.bf16.bf16.f32 "       \
                 "{%0,%1,%2,%3}, {%4,%5,%6,%7}, {%8,%9}, {%0,%1,%2,%3};"      \
                 : "+f"(D[0]), "+f"(D[1]), "+f"(D[2]), "+f"(D[3])             \
                 : "r"(A0), "r"(A1), "r"(A2), "r"(A3), "r"(B0), "r"(B1))

__device__ __forceinline__ uint32_t bf2_hi(float2 p) {
    __nv_bfloat162 h = __floats2bfloat162_rn(p.x, p.y);
    return *(uint32_t*)&h;
}
__device__ __forceinline__ uint32_t bf2_lo(float2 p, uint32_t hbits) {
    __nv_bfloat162 h = *(__nv_bfloat162*)&hbits;
    __nv_bfloat162 l = __floats2bfloat162_rn(p.x - __bfloat162float(h.x),
                                             p.y - __bfloat162float(h.y));
    return *(uint32_t*)&l;
}

__global__ __launch_bounds__(256, 2) void gemm_mma_kernel(const float* __restrict__ Z, int nrows) {
    extern __shared__ __align__(16) uint32_t sh[];
    uint32_t* WH = sh;                    // 128 x 68 words (bf16x2)
    uint32_t* WL = sh + 128 * PAD_W;

    int tid = threadIdx.x;

    // ---- stage W hi/lo into padded smem (8192 words each, coalesced) ----
    {
        const uint32_t* gwh = (const uint32_t*)g_Wh;
        const uint32_t* gwl = (const uint32_t*)g_Wl;
        #pragma unroll
        for (int i = 0; i < 32; i++) {
            int idx  = tid + 256 * i;        // 0..8191
            int row  = idx >> 6;
            int word = idx & 63;
            WH[row * PAD_W + word] = gwh[idx];
            WL[row * PAD_W + word] = gwl[idx];
        }
    }
    __syncthreads();

    int lane = tid & 31, w = tid >> 5;
    int g = lane >> 2, t = lane & 3;
    int r0 = (w & 3) * 32;        // warp row base within CTA tile
    int n0 = (w >> 2) * 64;       // warp col base

    // Per-thread A rows (clamped for OOB; garbage accumulators never stored)
    int base = blockIdx.x * 128 + r0 + g;
    int rA[4] = { base, base + 8, base + 16, base + 24 };
    const float* zp[4];
    #pragma unroll
    for (int q = 0; q < 4; q++) {
        int r = rA[q] < nrows ? rA[q] : (nrows - 1);
        zp[q] = Z + (size_t)r * HID + 2 * t;
    }

    float d[2][8][4];
    #pragma unroll
    for (int m = 0; m < 2; m++)
        #pragma unroll
        for (int n = 0; n < 8; n++)
            #pragma unroll
            for (int q = 0; q < 4; q++) d[m][n][q] = 0.f;

    #pragma unroll
    for (int ks = 0; ks < 8; ks++) {
        int kb = ks * 16;
        float2 p00 = *(const float2*)(zp[0] + kb);
        float2 p01 = *(const float2*)(zp[0] + kb + 8);
        float2 p10 = *(const float2*)(zp[1] + kb);
        float2 p11 = *(const float2*)(zp[1] + kb + 8);
        float2 q00 = *(const float2*)(zp[2] + kb);
        float2 q01 = *(const float2*)(zp[2] + kb + 8);
        float2 q10 = *(const float2*)(zp[3] + kb);
        float2 q11 = *(const float2*)(zp[3] + kb + 8);

        uint32_t ah[2][4], al[2][4];
        ah[0][0] = bf2_hi(p00);  ah[0][1] = bf2_hi(p10);
        ah[0][2] = bf2_hi(p01);  ah[0][3] = bf2_hi(p11);
        ah[1][0] = bf2_hi(q00);  ah[1][1] = bf2_hi(q10);
        ah[1][2] = bf2_hi(q01);  ah[1][3] = bf2_hi(q11);
        al[0][0] = bf2_lo(p00, ah[0][0]);  al[0][1] = bf2_lo(p10, ah[0][1]);
        al[0][2] = bf2_lo(p01, ah[0][2]);  al[0][3] = bf2_lo(p11, ah[0][3]);
        al[1][0] = bf2_lo(q00, ah[1][0]);  al[1][1] = bf2_lo(q10, ah[1][1]);
        al[1][2] = bf2_lo(q01, ah[1][2]);  al[1][3] = bf2_lo(q11, ah[1][3]);

        int kw = ks * 8 + t;
        #pragma unroll
        for (int n = 0; n < 8; n++) {
            int nb = (n0 + 8 * n + g) * PAD_W + kw;
            uint32_t bh0 = WH[nb], bh1 = WH[nb + 4];
            uint32_t bl0 = WL[nb], bl1 = WL[nb + 4];
            #pragma unroll
            for (int m = 0; m < 2; m++) {
                MMA16816(d[m][n], ah[m][0], ah[m][1], ah[m][2], ah[m][3], bh0, bh1);
                MMA16816(d[m][n], ah[m][0], ah[m][1], ah[m][2], ah[m][3], bl0, bl1);
                MMA16816(d[m][n], al[m][0], al[m][1], al[m][2], al[m][3], bh0, bh1);
            }
        }
    }

    // ---- epilogue: d -> g_Yh (fp16) ----
    #pragma unroll
    for (int m = 0; m < 2; m++) {
        int r = base + 16 * m;
        #pragma unroll
        for (int n = 0; n < 8; n++) {
            int c = n0 + 8 * n + 2 * t;
            if (r < nrows)
                *(__half2*)(g_Yh + (size_t)r * HID + c) = __floats2half2_rn(d[m][n][0], d[m][n][1]);
            if (r + 8 < nrows)
                *(__half2*)(g_Yh + (size_t)(r + 8) * HID + c) = __floats2half2_rn(d[m][n][2], d[m][n][3]);
        }
    }
}

// ------------------- kernel 3: per-edge gather + dot + sigmoid --------------
// 8 lanes/edge, 8 edges/warp. Lane handles elements [8s,8s+8) and [64+8s,64+8s+8).
// src Y in fp16 (2 LDG.128/edge/lane), dst Z fp32 (4 LDG.128/edge/lane).
__device__ __forceinline__ float dot16(uint4 A0, uint4 A1,
                                       float4 B0, float4 B1, float4 B2, float4 B3) {
    const __half2* h0 = (const __half2*)&A0;
    const __half2* h1 = (const __half2*)&A1;
    float2 f0 = __half22float2(h0[0]);
    float2 f1 = __half22float2(h0[1]);
    float2 f2 = __half22float2(h0[2]);
    float2 f3 = __half22float2(h0[3]);
    float2 g0 = __half22float2(h1[0]);
    float2 g1 = __half22float2(h1[1]);
    float2 g2 = __half22float2(h1[2]);
    float2 g3 = __half22float2(h1[3]);
    float v = f0.x * B0.x + f0.y * B0.y + f1.x * B0.z + f1.y * B0.w;
    v += f2.x * B1.x + f2.y * B1.y + f3.x * B1.z + f3.y * B1.w;
    v += g0.x * B2.x + g0.y * B2.y + g1.x * B2.z + g1.y * B2.w;
    v += g2.x * B3.x + g2.y * B3.y + g3.x * B3.z + g3.y * B3.w;
    return v;
}

__global__ __launch_bounds__(256) void edge_kernel(const void* __restrict__ ei,
                                                   const float* __restrict__ Z,
                                                   float* __restrict__ out, int E) {
    const unsigned FULL = 0xFFFFFFFFu;
    int gtid  = blockIdx.x * blockDim.x + threadIdx.x;
    int warp  = gtid >> 5;
    int lane  = gtid & 31;
    int grp   = lane >> 3;       // 0..3
    int sub   = lane & 7;        // 0..7

    long long e0 = (long long)warp * 8;
    if (e0 >= E) return;

    long long myidx = 0;
    int is64 = g_is64;
    if (lane < 16) {
        long long e = e0 + (lane & 7);
        if (e >= E) e = 0;
        size_t off = (lane < 8) ? (size_t)e : (size_t)E + (size_t)e;
        if (is64) myidx = ((const long long*)ei)[off];
        else      myidx = ((const int*)ei)[off];
    }
    long long s0 = __shfl_sync(FULL, myidx, grp);
    long long s1 = __shfl_sync(FULL, myidx, 4 + grp);
    long long d0 = __shfl_sync(FULL, myidx, 8 + grp);
    long long d1 = __shfl_sync(FULL, myidx, 12 + grp);

    const uint4*  Ya0 = (const uint4*)(g_Yh + (size_t)s0 * HID);
    const float4* Zb0 = (const float4*)(Z   + (size_t)d0 * HID);
    const uint4*  Ya1 = (const uint4*)(g_Yh + (size_t)s1 * HID);
    const float4* Zb1 = (const float4*)(Z   + (size_t)d1 * HID);

    // ---- 12 independent LDG.128 (4 fp16-src + 8 fp32-dst) ----
    uint4  A00 = Ya0[sub];          uint4  A01 = Ya0[sub + 8];
    float4 B00 = Zb0[2 * sub];      float4 B01 = Zb0[2 * sub + 1];
    float4 B02 = Zb0[16 + 2 * sub]; float4 B03 = Zb0[17 + 2 * sub];
    uint4  A10 = Ya1[sub];          uint4  A11 = Ya1[sub + 8];
    float4 B10 = Zb1[2 * sub];      float4 B11 = Zb1[2 * sub + 1];
    float4 B12 = Zb1[16 + 2 * sub]; float4 B13 = Zb1[17 + 2 * sub];

    float v0 = dot16(A00, A01, B00, B01, B02, B03);
    float v1 = dot16(A10, A11, B10, B11, B12, B13);

    v0 += __shfl_xor_sync(FULL, v0, 1);
    v1 += __shfl_xor_sync(FULL, v1, 1);
    v0 += __shfl_xor_sync(FULL, v0, 2);
    v1 += __shfl_xor_sync(FULL, v1, 2);
    v0 += __shfl_xor_sync(FULL, v0, 4);
    v1 += __shfl_xor_sync(FULL, v1, 4);

    float vg0 = __shfl_sync(FULL, v0, (lane & 3) << 3);
    float vg1 = __shfl_sync(FULL, v1, (lane & 3) << 3);
    float vg  = (lane < 4) ? vg0 : vg1;

    if (lane < 8) {
        long long e = e0 + lane;
        if (e < E) out[e] = 1.0f / (1.0f + expf(-vg));
    }
}

// ---------------------------------------------------------------------------
extern "C" void kernel_launch(void* const* d_in, const int* in_sizes, int n_in,
                              void* d_out, int out_size) {
    // Map inputs by element count: W = 16384; z = largest; edge_index = the rest.
    int wi = -1;
    for (int i = 0; i < n_in; i++) if (in_sizes[i] == HID * HID) { wi = i; break; }
    int zi = -1;
    for (int i = 0; i < n_in; i++) {
        if (i == wi) continue;
        if (zi < 0 || in_sizes[i] > in_sizes[zi]) zi = i;
    }
    int eii = -1;
    for (int i = 0; i < n_in; i++) if (i != wi && i != zi) { eii = i; break; }

    const float* W  = (const float*)d_in[wi];
    const float* z  = (const float*)d_in[zi];
    const void*  ei = d_in[eii];

    float* out = (float*)d_out;
    int nrows = in_sizes[zi] / HID;
    int E     = in_sizes[eii] / 2;

    symm_kernel<<<64, 256>>>(W, (const int*)ei);

    int smem = 2 * 128 * PAD_W * (int)sizeof(uint32_t);   // 69632 B
    cudaFuncSetAttribute(gemm_mma_kernel, cudaFuncAttributeMaxDynamicSharedMemorySize, smem);
    int gblocks = (nrows + 127) / 128;
    gemm_mma_kernel<<<gblocks, 256, smem>>>(z, nrows);

    int eblocks = (E + 63) / 64;
    edge_kernel<<<eblocks, 256>>>(ei, z, out, E);
}